// round 13
// baseline (speedup 1.0000x reference)
#include <cuda_runtime.h>

#define NN 50000
#define NE 800000

// ---- Scratch (__device__ globals; no allocation allowed) ----
__device__ float g_hp[NN * 128];     // relu(fc_pool(h))
__device__ float g_neigh[NN * 128];  // segment-max result
__device__ float g_h1[NN * 128];     // layer-1 output (first NN*64 used)
__device__ float g_h2[NN * 128];     // layer-2 output
__device__ int   g_deg[NN];          // in-degree histogram
__device__ int   g_off[NN + 1];      // CSR offsets (exclusive scan)
__device__ int   g_cur[NN];          // scatter cursors
__device__ int2  g_edge[NE];         // packed (src, float_as_int(ew)) sorted by dst

// Device-side buffer selection (keeps kernel_launch launches-only).
// sel: 0 -> g_h1, 1 -> g_h2, 2 -> external, 3 -> g_hp.
__device__ __forceinline__ float* buf_sel(int sel, float* ext) {
    return sel == 0 ? g_h1 : (sel == 1 ? g_h2 : (sel == 3 ? g_hp : ext));
}
__device__ __forceinline__ const float* cbuf_sel(int sel, const float* ext) {
    return sel == 0 ? g_h1 : (sel == 1 ? g_h2 : ext);
}

__device__ __forceinline__ unsigned f2tf32(float v) {
    unsigned r;
    asm("cvt.rna.tf32.f32 %0, %1;" : "=r"(r) : "f"(v));
    return r;
}

__device__ __forceinline__ void mma_tf32(float& c0, float& c1, float& c2, float& c3,
                                         unsigned a0, unsigned a1, unsigned a2, unsigned a3,
                                         unsigned b0, unsigned b1) {
    asm("mma.sync.aligned.m16n8k8.row.col.f32.tf32.tf32.f32 "
        "{%0,%1,%2,%3}, {%4,%5,%6,%7}, {%8,%9}, {%0,%1,%2,%3};"
        : "+f"(c0), "+f"(c1), "+f"(c2), "+f"(c3)
        : "r"(a0), "r"(a1), "r"(a2), "r"(a3), "r"(b0), "r"(b1));
}

// ===========================================================================
// CSR construction (once per launch; reused by all 3 layers)
// ===========================================================================
__global__ void zero_counters_kernel() {
    int i = blockIdx.x * blockDim.x + threadIdx.x;
    if (i < NN) { g_deg[i] = 0; g_cur[i] = 0; }
}

__global__ void histogram_kernel(const int* __restrict__ dst) {
    int e = blockIdx.x * blockDim.x + threadIdx.x;
    if (e < NE) atomicAdd(&g_deg[dst[e]], 1);
}

// Chunked exclusive scan: each of 1024 threads owns a contiguous chunk.
__global__ void scan_kernel() {
    const int T = 1024;
    const int CH = (NN + T - 1) / T;  // 49
    __shared__ int s[T];
    int tid = threadIdx.x;
    int lo = tid * CH;
    int hi = min(lo + CH, NN);
    int sum = 0;
    for (int i = lo; i < hi; i++) sum += g_deg[i];
    s[tid] = sum;
    __syncthreads();
#pragma unroll
    for (int off = 1; off < T; off <<= 1) {
        int t = (tid >= off) ? s[tid - off] : 0;
        __syncthreads();
        s[tid] += t;
        __syncthreads();
    }
    int run = s[tid] - sum;  // exclusive prefix of this chunk
    for (int i = lo; i < hi; i++) {
        g_off[i] = run;
        run += g_deg[i];
    }
    if (tid == T - 1) g_off[NN] = run;
}

__global__ void scatter_edges_kernel(const int* __restrict__ src,
                                     const int* __restrict__ dst,
                                     const float* __restrict__ ew) {
    int e = blockIdx.x * blockDim.x + threadIdx.x;
    if (e < NE) {
        int d = dst[e];
        int p = g_off[d] + atomicAdd(&g_cur[d], 1);
        g_edge[p] = make_int2(src[e], __float_as_int(ew[e]));
    }
}

// ===========================================================================
// Error-compensated tf32 tensor-core GEMM (3-term split: hi*hi + lo*hi + hi*lo):
//   out[row, n] = relu( sum_k X[row,k] * W[k,n] + bias[n] )   (~fp32 accuracy)
// X = s1 (K = DIN) or [s1 | g_neigh] (K = 2*DIN, TWO=true); W = Wa or [Wa ; Wb].
// Block: 128 threads (4 warps). Block tile 64 rows x N. Warp tile 16 x N.
// KT=16 for N=128 keeps static smem under 48KB (27.1KB); KT=32 for N=64 (35.8KB).
// ===========================================================================
template <int KTOT, int N, bool TWO>
__global__ void __launch_bounds__(128) mma_fc_kernel(
    int hsel, const float* __restrict__ hext,
    const float* __restrict__ Wa, const float* __restrict__ Wb,
    const float* __restrict__ bias,
    int osel, float* __restrict__ oext) {
    constexpr int KT = (N == 128) ? 16 : 32;
    constexpr int DIN = TWO ? KTOT / 2 : KTOT;
    constexpr int XS = KT + 4;   // padded X row stride
    constexpr int WS = N + 4;    // padded W row stride
    constexpr int NT = N / 8;    // n-tiles per warp
    static_assert(KTOT % KT == 0, "K tiling");

    __shared__ unsigned xh[64 * XS];
    __shared__ unsigned xl[64 * XS];
    __shared__ unsigned wh[KT * WS];
    __shared__ unsigned wl[KT * WS];

    const float* __restrict__ s1 = cbuf_sel(hsel, hext);
    float* __restrict__ outp = buf_sel(osel, oext);

    const int row0 = blockIdx.x * 64;
    const int tid = threadIdx.x;
    const int wid = tid >> 5;
    const int lane = tid & 31;
    const int tq = lane >> 2;  // 0..7
    const int tr = lane & 3;   // 0..3

    float acc[NT][4];
#pragma unroll
    for (int nt = 0; nt < NT; nt++)
#pragma unroll
        for (int q = 0; q < 4; q++) acc[nt][q] = 0.0f;

    for (int k0 = 0; k0 < KTOT; k0 += KT) {
        __syncthreads();
        // ---- fill X tile (64 rows x KT), split hi/lo ----
        for (int i = tid; i < 64 * KT; i += 128) {
            int r = i / KT;
            int kk = i % KT;
            int row = min(row0 + r, NN - 1);
            int k = k0 + kk;
            float v;
            if (TWO)
                v = (k < DIN) ? s1[row * DIN + k] : g_neigh[row * DIN + (k - DIN)];
            else
                v = s1[row * DIN + k];
            unsigned hi = f2tf32(v);
            xh[r * XS + kk] = hi;
            xl[r * XS + kk] = f2tf32(v - __uint_as_float(hi));
        }
        // ---- fill W tile (KT x N), split hi/lo ----
        for (int i = tid; i < KT * N; i += 128) {
            int kk = i / N;
            int n = i % N;
            int k = k0 + kk;
            float v = (TWO && k >= DIN) ? Wb[(k - DIN) * N + n] : Wa[k * N + n];
            unsigned hi = f2tf32(v);
            wh[kk * WS + n] = hi;
            wl[kk * WS + n] = f2tf32(v - __uint_as_float(hi));
        }
        __syncthreads();
        // ---- mma over this K tile: hi*hi + lo*hi + hi*lo ----
#pragma unroll
        for (int kk8 = 0; kk8 < KT; kk8 += 8) {
            const int xoff = (wid * 16 + tq) * XS + kk8 + tr;
            unsigned a0h = xh[xoff],          a2h = xh[xoff + 4];
            unsigned a1h = xh[xoff + 8 * XS], a3h = xh[xoff + 8 * XS + 4];
            unsigned a0l = xl[xoff],          a2l = xl[xoff + 4];
            unsigned a1l = xl[xoff + 8 * XS], a3l = xl[xoff + 8 * XS + 4];
#pragma unroll
            for (int nt = 0; nt < NT; nt++) {
                const int woff = (kk8 + tr) * WS + nt * 8 + tq;
                unsigned b0h = wh[woff], b1h = wh[woff + 4 * WS];
                unsigned b0l = wl[woff], b1l = wl[woff + 4 * WS];
                mma_tf32(acc[nt][0], acc[nt][1], acc[nt][2], acc[nt][3],
                         a0h, a1h, a2h, a3h, b0h, b1h);
                mma_tf32(acc[nt][0], acc[nt][1], acc[nt][2], acc[nt][3],
                         a0l, a1l, a2l, a3l, b0h, b1h);
                mma_tf32(acc[nt][0], acc[nt][1], acc[nt][2], acc[nt][3],
                         a0h, a1h, a2h, a3h, b0l, b1l);
            }
        }
    }

    // ---- epilogue: bias + relu + store ----
    const int ra = row0 + wid * 16 + tq;
    const int rb = ra + 8;
#pragma unroll
    for (int nt = 0; nt < NT; nt++) {
        int col = nt * 8 + 2 * tr;
        float bb0 = bias[col];
        float bb1 = bias[col + 1];
        if (ra < NN) {
            float2 v = make_float2(fmaxf(acc[nt][0] + bb0, 0.0f),
                                   fmaxf(acc[nt][1] + bb1, 0.0f));
            *reinterpret_cast<float2*>(&outp[ra * N + col]) = v;
        }
        if (rb < NN) {
            float2 v = make_float2(fmaxf(acc[nt][2] + bb0, 0.0f),
                                   fmaxf(acc[nt][3] + bb1, 0.0f));
            *reinterpret_cast<float2*>(&outp[rb * N + col]) = v;
        }
    }
}

// ===========================================================================
// Per-node segment max over CSR in-edges. One thread = 4 columns (float4),
// D/4 threads per node. Packed (src, ew) records: one 8B load per edge.
// Empty segment -> 0 (messages >= 0; isfinite->0 rule).
// ===========================================================================
template <int D>
__global__ void segment_max_kernel() {
    constexpr int TPN = D / 4;                 // threads per node
    constexpr int NPB = 128 / TPN;             // nodes per block
    const int node = blockIdx.x * NPB + threadIdx.x / TPN;
    const int lane = threadIdx.x % TPN;
    if (node >= NN) return;
    const float4* __restrict__ hp4 = reinterpret_cast<const float4*>(g_hp);
    int i = g_off[node];
    const int end = g_off[node + 1];
    float4 m = make_float4(0.f, 0.f, 0.f, 0.f);
    for (; i + 3 < end; i += 4) {
        int2 e0 = g_edge[i], e1 = g_edge[i + 1], e2 = g_edge[i + 2], e3 = g_edge[i + 3];
        float w0 = __int_as_float(e0.y), w1 = __int_as_float(e1.y);
        float w2 = __int_as_float(e2.y), w3 = __int_as_float(e3.y);
        float4 v0 = hp4[e0.x * TPN + lane];
        float4 v1 = hp4[e1.x * TPN + lane];
        float4 v2 = hp4[e2.x * TPN + lane];
        float4 v3 = hp4[e3.x * TPN + lane];
        m.x = fmaxf(fmaxf(m.x, v0.x * w0), fmaxf(fmaxf(v1.x * w1, v2.x * w2), v3.x * w3));
        m.y = fmaxf(fmaxf(m.y, v0.y * w0), fmaxf(fmaxf(v1.y * w1, v2.y * w2), v3.y * w3));
        m.z = fmaxf(fmaxf(m.z, v0.z * w0), fmaxf(fmaxf(v1.z * w1, v2.z * w2), v3.z * w3));
        m.w = fmaxf(fmaxf(m.w, v0.w * w0), fmaxf(fmaxf(v1.w * w1, v2.w * w2), v3.w * w3));
    }
    for (; i < end; i++) {
        int2 e = g_edge[i];
        float w = __int_as_float(e.y);
        float4 v = hp4[e.x * TPN + lane];
        m.x = fmaxf(m.x, v.x * w);
        m.y = fmaxf(m.y, v.y * w);
        m.z = fmaxf(m.z, v.z * w);
        m.w = fmaxf(m.w, v.w * w);
    }
    reinterpret_cast<float4*>(g_neigh)[node * TPN + lane] = m;
}

static inline int cdiv(long a, int b) { return (int)((a + b - 1) / b); }

extern "C" void kernel_launch(void* const* d_in, const int* in_sizes, int n_in,
                              void* d_out, int out_size) {
    const float* feat = (const float*)d_in[0];
    const int*   src  = (const int*)d_in[1];
    const int*   dst  = (const int*)d_in[2];
    const float* ew   = (const float*)d_in[3];

    const float* Wp1 = (const float*)d_in[4];
    const float* bp1 = (const float*)d_in[5];
    const float* Ws1 = (const float*)d_in[6];
    const float* Wn1 = (const float*)d_in[7];
    const float* b1  = (const float*)d_in[8];

    const float* Wp2 = (const float*)d_in[9];
    const float* bp2 = (const float*)d_in[10];
    const float* Ws2 = (const float*)d_in[11];
    const float* Wn2 = (const float*)d_in[12];
    const float* b2  = (const float*)d_in[13];

    const float* Wp3 = (const float*)d_in[14];
    const float* bp3 = (const float*)d_in[15];
    const float* Ws3 = (const float*)d_in[16];
    const float* Wn3 = (const float*)d_in[17];
    const float* b3  = (const float*)d_in[18];

    float* out = (float*)d_out;
    const int MB = cdiv(NN, 64);  // 782 row-blocks

    // ---- Build CSR (dst-sorted edges), reused by all layers ----
    zero_counters_kernel<<<cdiv(NN, 256), 256>>>();
    histogram_kernel<<<cdiv(NE, 256), 256>>>(dst);
    scan_kernel<<<1, 1024>>>();
    scatter_edges_kernel<<<cdiv(NE, 256), 256>>>(src, dst, ew);

    // ---------------- Layer 1: Din=128, Dout=64 (feat -> g_h1) ------------
    mma_fc_kernel<128, 128, false><<<MB, 128>>>(2, feat, Wp1, nullptr, bp1, 3, nullptr);
    segment_max_kernel<128><<<NN / 4, 128>>>();
    mma_fc_kernel<256, 64, true><<<MB, 128>>>(2, feat, Ws1, Wn1, b1, 0, nullptr);

    // ---------------- Layer 2: Din=64, Dout=128 (g_h1 -> g_h2) ------------
    mma_fc_kernel<64, 64, false><<<MB, 128>>>(0, nullptr, Wp2, nullptr, bp2, 3, nullptr);
    segment_max_kernel<64><<<NN / 8, 128>>>();
    mma_fc_kernel<128, 128, true><<<MB, 128>>>(0, nullptr, Ws2, Wn2, b2, 1, nullptr);

    // ---------------- Layer 3: Din=128, Dout=128 (g_h2 -> out) ------------
    mma_fc_kernel<128, 128, false><<<MB, 128>>>(1, nullptr, Wp3, nullptr, bp3, 3, nullptr);
    segment_max_kernel<128><<<NN / 4, 128>>>();
    mma_fc_kernel<256, 128, true><<<MB, 128>>>(1, nullptr, Ws3, Wn3, b3, 2, out);
}